// round 4
// baseline (speedup 1.0000x reference)
#include <cuda_runtime.h>
#include <cuda_bf16.h>
#include <cstdint>
#include <math.h>

#define B_ 32
#define T_ 128
#define L_ 512
#define D_ 256
#define V_ 32000

// ---------------- device scratch (static, no allocations) ----------------
__device__ float g_emb[T_*B_*D_];              // [t*32+b][256]
__device__ float g_gx[2][(size_t)T_*768*B_];   // [dir][t][768][32]
__device__ float g_outsT[512*(size_t)T_*B_];   // [c][t*32+b]  c:0..255 ys_f, 256..511 ys_b(rev)
__device__ float g_hx[2][B_*D_];               // h exchange, b-major: [dir][b*256+d]
__device__ float g_rnn[(size_t)T_*B_*D_];      // [t*32+b][256]
__device__ float g_hidden[B_*D_];
__device__ float g_u[B_*D_];
__device__ float g_E[4ull*B_*L_*D_];           // [hop_table][b][l][d]  (64MB)
__device__ float g_prob[B_*L_];
__device__ unsigned g_flags[2][64*32];         // [dir][slice*32], 128B-padded flags

// ---------------- f32x2 helpers ----------------
__device__ __forceinline__ unsigned long long ffma2(unsigned long long a,
                                                    unsigned long long b,
                                                    unsigned long long c) {
    unsigned long long d;
    asm("fma.rn.f32x2 %0, %1, %2, %3;" : "=l"(d) : "l"(a), "l"(b), "l"(c));
    return d;
}
__device__ __forceinline__ float f2sum(unsigned long long v) {
    float lo, hi;
    asm("mov.b64 {%0, %1}, %2;" : "=f"(lo), "=f"(hi) : "l"(v));
    return lo + hi;
}

// ---------------- conv embedding bag (block 0 also zeroes flags) ----------------
__global__ void embed_conv_kernel(const int* __restrict__ conv, const float* __restrict__ table) {
    int bx = blockIdx.x;            // t*32 + b
    int t = bx >> 5, b = bx & 31;
    int tid = threadIdx.x;          // 64 threads, one float4 each
    if (bx == 0) {
        for (int i = tid; i < 2*64*32; i += 64) g_flags[i >> 11][i & 2047] = 0;
    }
    int4 c = ((const int4*)conv)[b*T_ + t];
    const float4* T4 = (const float4*)table;
    float4 v = make_float4(0.f,0.f,0.f,0.f);
    int idx[4] = {c.x, c.y, c.z, c.w};
    #pragma unroll
    for (int m = 0; m < 4; ++m) {
        float4 e = T4[(size_t)idx[m]*64 + tid];
        v.x += e.x; v.y += e.y; v.z += e.z; v.w += e.w;
    }
    ((float4*)g_emb)[(size_t)bx*64 + tid] = v;
}

// ---------------- fp32 GEMM: C = A @ W^T + bias ----------------
template<int AT, int GX, int SRC, int DST>
__global__ void __launch_bounds__(256) gemm_kernel(
        const float* __restrict__ W, const float* __restrict__ bias,
        int M, int N, int K) {
    const float* A = (SRC == 0) ? g_emb : g_outsT;
    float* C = (DST == 0) ? g_gx[0] : (DST == 1) ? g_gx[1] : g_rnn;
    __shared__ float As[16][64];
    __shared__ float Bs[16][64];
    int tid = threadIdx.x;
    int n0 = blockIdx.x * 64, m0 = blockIdx.y * 64;
    int ty = tid >> 4, tx = tid & 15;
    float acc[4][4];
    #pragma unroll
    for (int i = 0; i < 4; ++i)
        #pragma unroll
        for (int j = 0; j < 4; ++j) acc[i][j] = 0.f;

    for (int k0 = 0; k0 < K; k0 += 16) {
        if (AT == 0) {
            int m = tid >> 2, kk = (tid & 3) * 4;
            float4 a = *(const float4*)&A[(size_t)(m0+m)*K + k0 + kk];
            As[kk+0][m] = a.x; As[kk+1][m] = a.y; As[kk+2][m] = a.z; As[kk+3][m] = a.w;
        } else {
            int k = tid >> 4, m4 = (tid & 15) * 4;
            float4 a = *(const float4*)&A[(size_t)(k0+k)*M + m0 + m4];
            *(float4*)&As[k][m4] = a;
        }
        {
            int n = tid >> 2, kk = (tid & 3) * 4;
            float4 w = *(const float4*)&W[(size_t)(n0+n)*K + k0 + kk];
            Bs[kk+0][n] = w.x; Bs[kk+1][n] = w.y; Bs[kk+2][n] = w.z; Bs[kk+3][n] = w.w;
        }
        __syncthreads();
        #pragma unroll
        for (int kk = 0; kk < 16; ++kk) {
            float a[4], bb[4];
            #pragma unroll
            for (int j = 0; j < 4; ++j) { a[j] = As[kk][ty*4+j]; bb[j] = Bs[kk][tx*4+j]; }
            #pragma unroll
            for (int i = 0; i < 4; ++i)
                #pragma unroll
                for (int j = 0; j < 4; ++j) acc[i][j] = fmaf(a[i], bb[j], acc[i][j]);
        }
        __syncthreads();
    }
    #pragma unroll
    for (int i = 0; i < 4; ++i) {
        #pragma unroll
        for (int j = 0; j < 4; ++j) {
            int m = m0 + ty*4 + i, n = n0 + tx*4 + j;
            float v = acc[i][j] + bias[n];
            if (GX) C[(size_t)(m >> 5)*((size_t)N*32) + (size_t)n*32 + (m & 31)] = v;
            else    C[(size_t)m*N + n] = v;
        }
    }
}

// ---------------- GRU: 128 blocks (64 d-slices/dir), smem-stationary Whh, f32x2 ----------------
__global__ void __launch_bounds__(128, 1) gru_kernel(
        const float* __restrict__ Whh_f, const float* __restrict__ Whh_b,
        const float* __restrict__ bhh_f, const float* __restrict__ bhh_b) {
    int blk = blockIdx.x;
    int dir = blk >> 6;
    int slice = blk & 63;
    int d0 = slice * 4;
    int tid = threadIdx.x;
    int di = tid >> 5;        // warp id == d offset within slice
    int b  = tid & 31;        // lane == batch
    int d  = d0 + di;

    const float* Whh = dir ? Whh_b : Whh_f;
    const float* bhh = dir ? bhh_b : bhh_f;
    const float* gx  = g_gx[dir];

    __shared__ __align__(16) float w_s[12*256];     // [g*4 + di][k]
    __shared__ __align__(16) float h_s[32*260];     // [b][k], pad 260 (conflict-free, 16B aligned)
    __shared__ float bsh[12];

    for (int i = tid; i < 3072; i += 128) {
        int g = i >> 10; int r = i & 1023; int dd = r >> 8; int k = r & 255;
        w_s[(g*4 + dd)*256 + k] = Whh[(size_t)(g*256 + d0 + dd)*256 + k];
    }
    if (tid < 12) { int g = tid >> 2, dd = tid & 3; bsh[tid] = bhh[g*256 + d0 + dd]; }
    __syncthreads();

    float biasR = bsh[0*4 + di], biasZ = bsh[1*4 + di], biasN = bsh[2*4 + di];
    const ulonglong2* wr2 = (const ulonglong2*)&w_s[(0*4 + di)*256];
    const ulonglong2* wz2 = (const ulonglong2*)&w_s[(1*4 + di)*256];
    const ulonglong2* wn2 = (const ulonglong2*)&w_s[(2*4 + di)*256];
    volatile unsigned* myflag = &g_flags[dir][slice*32];
    const unsigned* poll0 = &g_flags[dir][(2*(tid & 31) + 0)*32];
    const unsigned* poll1 = &g_flags[dir][(2*(tid & 31) + 1)*32];
    float* hx = g_hx[dir];

    for (int s = 0; s < T_; ++s) {
        int t = dir ? (T_-1 - s) : s;
        // hoist gx loads (independent of h) above the wait
        const float* gxt = gx + (size_t)t*768*32;
        float xr = gxt[(0*256 + d)*32 + b];
        float xz = gxt[(1*256 + d)*32 + b];
        float xn = gxt[(2*256 + d)*32 + b];

        float aRf = 0.f, aZf = 0.f, aNf = 0.f, hprev = 0.f;

        if (s > 0) {
            // warp0: low-traffic relaxed poll with backoff (32 threads x 2 flags)
            if (tid < 32) {
                unsigned v0, v1;
                for (;;) {
                    asm volatile("ld.relaxed.gpu.u32 %0, [%1];" : "=r"(v0) : "l"(poll0) : "memory");
                    asm volatile("ld.relaxed.gpu.u32 %0, [%1];" : "=r"(v1) : "l"(poll1) : "memory");
                    if (v0 >= (unsigned)s && v1 >= (unsigned)s) break;
                    __nanosleep(50);
                }
                __threadfence();   // acquire side of fence-to-fence sync
            }
            __syncthreads();
            // stage h (b-major) into smem: coalesced __ldcg + conflict-free STS
            const float4* hx4 = (const float4*)hx;
            #pragma unroll
            for (int i = 0; i < 16; ++i) {
                int idx = tid + i*128;            // 2048 float4s
                float4 hv = __ldcg(&hx4[idx]);
                int bb = idx >> 6, c = idx & 63;
                *(float4*)&h_s[bb*260 + c*4] = hv;
            }
            __syncthreads();

            const ulonglong2* hp = (const ulonglong2*)&h_s[b*260];
            unsigned long long aR = 0ull, aZ = 0ull, aN = 0ull;
            #pragma unroll 8
            for (int k = 0; k < 64; ++k) {
                ulonglong2 hv = hp[k];
                ulonglong2 r2 = wr2[k], z2 = wz2[k], n2 = wn2[k];
                aR = ffma2(hv.x, r2.x, aR); aR = ffma2(hv.y, r2.y, aR);
                aZ = ffma2(hv.x, z2.x, aZ); aZ = ffma2(hv.y, z2.y, aZ);
                aN = ffma2(hv.x, n2.x, aN); aN = ffma2(hv.y, n2.y, aN);
            }
            aRf = f2sum(aR); aZf = f2sum(aZ); aNf = f2sum(aN);
            hprev = h_s[b*260 + d];
        }

        float r = 1.f / (1.f + __expf(-(xr + aRf + biasR)));
        float z = 1.f / (1.f + __expf(-(xz + aZf + biasZ)));
        float narg = xn + r * (aNf + biasN);
        float e2 = __expf(2.f * narg);
        float n = (e2 - 1.f) / (e2 + 1.f);
        float h2 = (1.f - z) * n + z * hprev;

        hx[b*256 + d] = h2;                      // critical-path exchange store first
        g_outsT[(size_t)(dir*256 + d)*4096 + t*32 + b] = h2;
        __threadfence();                          // release side
        __syncthreads();
        if (tid == 0) *myflag = (unsigned)(s + 1);
    }
}

// ---------------- hidden = concat(hT_f, hT_b) @ W_w^T + W_b ; u = hidden ----------------
__global__ void hidden_kernel(const float* __restrict__ W_w, const float* __restrict__ W_b) {
    int b = blockIdx.x;
    int tid = threadIdx.x, wid = tid >> 5, lane = tid & 31;
    __shared__ float a_s[512];
    a_s[tid]       = g_outsT[(size_t)tid*4096 + (T_-1)*32 + b];      // hT_f
    a_s[256 + tid] = g_outsT[(size_t)(256 + tid)*4096 + 0*32 + b];   // hT_b (stored at t=0)
    __syncthreads();
    for (int dd = wid; dd < 256; dd += 8) {
        const float4* wrow = (const float4*)&W_w[(size_t)dd*512];
        float acc = 0.f;
        #pragma unroll
        for (int i = 0; i < 4; ++i) {
            float4 wv = wrow[lane + i*32];
            float4 av = *(const float4*)&a_s[(lane + i*32)*4];
            acc = fmaf(wv.x, av.x, acc); acc = fmaf(wv.y, av.y, acc);
            acc = fmaf(wv.z, av.z, acc); acc = fmaf(wv.w, av.w, acc);
        }
        #pragma unroll
        for (int o = 16; o > 0; o >>= 1) acc += __shfl_xor_sync(0xffffffffu, acc, o);
        if (lane == 0) {
            float v = acc + W_b[dd];
            g_hidden[b*256 + dd] = v;
            g_u[b*256 + dd] = v;
        }
    }
}

// ---------------- E[h][b][l][:] = embed_bag(C_tables[h]) + add_lm(rnn_out) ----------------
__global__ void ebuild_kernel(const int* __restrict__ src, const float* __restrict__ C,
                              const int* __restrict__ kb, const int* __restrict__ cl) {
    int bl = blockIdx.x;               // b*512 + l
    int b = bl >> 9, l = bl & 511;
    int tid = threadIdx.x;             // 64 threads, float4 each
    int4 s = ((const int4*)src)[bl];
    int rel = l - kb[b];
    bool valid = (rel >= 0) && (rel < cl[b]);
    int rc = min(max(rel, 0), T_ - 1);
    float4 base = make_float4(0.f,0.f,0.f,0.f);
    if (valid) base = ((const float4*)g_rnn)[(size_t)(rc*32 + b)*64 + tid];
    const float4* C4 = (const float4*)C;
    int idx[4] = {s.x, s.y, s.z, s.w};
    #pragma unroll
    for (int h = 0; h < 4; ++h) {
        float4 v = base;
        #pragma unroll
        for (int m = 0; m < 4; ++m) {
            float4 e = C4[((size_t)h*V_ + idx[m])*64 + tid];
            v.x += e.x; v.y += e.y; v.z += e.z; v.w += e.w;
        }
        ((float4*)g_E)[(((size_t)h*B_ + b)*L_ + l)*64 + tid] = v;
    }
}

// ---------------- hop: logits + softmax (+ sigmoid to d_out on last hop) ----------------
__global__ void hop_logit_kernel(int hop, float* __restrict__ out) {
    int b = blockIdx.x;
    int tid = threadIdx.x, wid = tid >> 5, lane = tid & 31;
    __shared__ float u_s[256];
    __shared__ float logit_s[512];
    __shared__ float red_s[8];
    u_s[tid] = g_u[b*256 + tid];
    __syncthreads();
    const float4* u4 = (const float4*)u_s;
    for (int l = wid; l < 512; l += 8) {
        const float4* row = (const float4*)&g_E[(((size_t)hop*B_ + b)*L_ + l)*D_];
        float acc = 0.f;
        #pragma unroll
        for (int i = 0; i < 2; ++i) {
            float4 e = row[lane + i*32];
            float4 uu = u4[lane + i*32];
            acc = fmaf(e.x, uu.x, acc); acc = fmaf(e.y, uu.y, acc);
            acc = fmaf(e.z, uu.z, acc); acc = fmaf(e.w, uu.w, acc);
        }
        #pragma unroll
        for (int o = 16; o > 0; o >>= 1) acc += __shfl_xor_sync(0xffffffffu, acc, o);
        if (lane == 0) logit_s[l] = acc;
    }
    __syncthreads();
    float l0 = logit_s[tid], l1 = logit_s[tid + 256];
    float m = fmaxf(l0, l1);
    #pragma unroll
    for (int o = 16; o > 0; o >>= 1) m = fmaxf(m, __shfl_xor_sync(0xffffffffu, m, o));
    if (lane == 0) red_s[wid] = m;
    __syncthreads();
    float M = red_s[0];
    #pragma unroll
    for (int i = 1; i < 8; ++i) M = fmaxf(M, red_s[i]);
    __syncthreads();
    float e0 = expf(l0 - M), e1 = expf(l1 - M);
    float ssum = e0 + e1;
    #pragma unroll
    for (int o = 16; o > 0; o >>= 1) ssum += __shfl_xor_sync(0xffffffffu, ssum, o);
    if (lane == 0) red_s[wid] = ssum;
    __syncthreads();
    float S = 0.f;
    #pragma unroll
    for (int i = 0; i < 8; ++i) S += red_s[i];
    float inv = 1.f / S;
    g_prob[b*512 + tid]       = e0 * inv;
    g_prob[b*512 + tid + 256] = e1 * inv;
    if (hop == 2) {
        out[b*512 + tid]       = 1.f / (1.f + expf(-l0));
        out[b*512 + tid + 256] = 1.f / (1.f + expf(-l1));
    }
}

// ---------------- hop: u += E[hop+1]^T @ prob ----------------
__global__ void hop_agg_kernel(int hop) {
    int b = blockIdx.x, d = threadIdx.x;   // 256 threads
    __shared__ float p_s[512];
    p_s[d]       = g_prob[b*512 + d];
    p_s[d + 256] = g_prob[b*512 + d + 256];
    __syncthreads();
    const float* E = &g_E[(((size_t)(hop+1)*B_ + b)*L_)*D_];
    float acc = 0.f;
    #pragma unroll 8
    for (int l = 0; l < 512; ++l) acc = fmaf(p_s[l], E[(size_t)l*256 + d], acc);
    g_u[b*256 + d] += acc;
}

// ---------------- encoded = relu(concat(hidden, u) @ proj^T + pb) ----------------
__global__ void encoded_kernel(const float* __restrict__ pw, const float* __restrict__ pb,
                               float* __restrict__ out) {
    int b = blockIdx.x;
    int tid = threadIdx.x, wid = tid >> 5, lane = tid & 31;
    __shared__ float a_s[512];
    a_s[tid]       = g_hidden[b*256 + tid];
    a_s[256 + tid] = g_u[b*256 + tid];
    __syncthreads();
    for (int dd = wid; dd < 256; dd += 8) {
        const float4* wrow = (const float4*)&pw[(size_t)dd*512];
        float acc = 0.f;
        #pragma unroll
        for (int i = 0; i < 4; ++i) {
            float4 wv = wrow[lane + i*32];
            float4 av = *(const float4*)&a_s[(lane + i*32)*4];
            acc = fmaf(wv.x, av.x, acc); acc = fmaf(wv.y, av.y, acc);
            acc = fmaf(wv.z, av.z, acc); acc = fmaf(wv.w, av.w, acc);
        }
        #pragma unroll
        for (int o = 16; o > 0; o >>= 1) acc += __shfl_xor_sync(0xffffffffu, acc, o);
        if (lane == 0) out[16384 + b*256 + dd] = fmaxf(acc + pb[dd], 0.f);
    }
}

// ---------------- launch ----------------
extern "C" void kernel_launch(void* const* d_in, const int* in_sizes, int n_in,
                              void* d_out, int out_size) {
    const int*   conv_seqs = (const int*)  d_in[0];
    const int*   src_seqs  = (const int*)  d_in[1];
    const int*   kb_len    = (const int*)  d_in[2];
    const int*   conv_len  = (const int*)  d_in[3];
    const float* emb_ctx   = (const float*)d_in[4];
    const float* C_tables  = (const float*)d_in[5];
    const float* Wih_f     = (const float*)d_in[6];
    const float* Whh_f     = (const float*)d_in[7];
    const float* bih_f     = (const float*)d_in[8];
    const float* bhh_f     = (const float*)d_in[9];
    const float* Wih_b     = (const float*)d_in[10];
    const float* Whh_b     = (const float*)d_in[11];
    const float* bih_b     = (const float*)d_in[12];
    const float* bhh_b     = (const float*)d_in[13];
    const float* W_w       = (const float*)d_in[14];
    const float* W_b       = (const float*)d_in[15];
    const float* proj_w    = (const float*)d_in[16];
    const float* proj_b    = (const float*)d_in[17];
    float* out = (float*)d_out;

    embed_conv_kernel<<<T_*B_, 64>>>(conv_seqs, emb_ctx);
    gemm_kernel<0,1,0,0><<<dim3(12, 64), 256>>>(Wih_f, bih_f, 4096, 768, 256);
    gemm_kernel<0,1,0,1><<<dim3(12, 64), 256>>>(Wih_b, bih_b, 4096, 768, 256);
    gru_kernel<<<128, 128>>>(Whh_f, Whh_b, bhh_f, bhh_b);
    hidden_kernel<<<32, 256>>>(W_w, W_b);
    gemm_kernel<1,0,1,2><<<dim3(4, 64), 256>>>(W_w, W_b, 4096, 256, 512);
    ebuild_kernel<<<B_*L_, 64>>>(src_seqs, C_tables, kb_len, conv_len);
    for (int hop = 0; hop < 3; ++hop) {
        hop_logit_kernel<<<32, 256>>>(hop, out);
        hop_agg_kernel<<<32, 256>>>(hop);
    }
    encoded_kernel<<<32, 256>>>(proj_w, proj_b, out);
}

// round 5
// speedup vs baseline: 1.0936x; 1.0936x over previous
#include <cuda_runtime.h>
#include <cuda_bf16.h>
#include <cstdint>
#include <math.h>

#define B_ 32
#define T_ 128
#define L_ 512
#define D_ 256
#define V_ 32000

// ---------------- device scratch (static, no allocations) ----------------
__device__ float g_emb[T_*B_*D_];              // [t*32+b][256]
__device__ float g_gx[2][(size_t)T_*768*B_];   // [dir][t][768][32]
__device__ float g_outsT[512*(size_t)T_*B_];   // [c][t*32+b]  c:0..255 ys_f, 256..511 ys_b(rev)
__device__ float g_hx[2][2][B_*D_];            // h exchange, [dir][phase][b*256+d]
__device__ float g_rnn[(size_t)T_*B_*D_];      // [t*32+b][256]
__device__ float g_hidden[B_*D_];
__device__ float g_u[B_*D_];
__device__ float g_E[4ull*B_*L_*D_];           // [hop_table][b][l][d]  (64MB)
__device__ float g_prob[B_*L_];
__device__ unsigned g_flags[2][64*32];         // [dir][slice*32], 128B-padded flags

// ---------------- f32x2 helpers ----------------
__device__ __forceinline__ unsigned long long ffma2(unsigned long long a,
                                                    unsigned long long b,
                                                    unsigned long long c) {
    unsigned long long d;
    asm("fma.rn.f32x2 %0, %1, %2, %3;" : "=l"(d) : "l"(a), "l"(b), "l"(c));
    return d;
}
__device__ __forceinline__ float f2sum(unsigned long long v) {
    float lo, hi;
    asm("mov.b64 {%0, %1}, %2;" : "=f"(lo), "=f"(hi) : "l"(v));
    return lo + hi;
}

// ---------------- conv embedding bag (block 0 also zeroes flags) ----------------
__global__ void embed_conv_kernel(const int* __restrict__ conv, const float* __restrict__ table) {
    int bx = blockIdx.x;            // t*32 + b
    int t = bx >> 5, b = bx & 31;
    int tid = threadIdx.x;          // 64 threads, one float4 each
    if (bx == 0) {
        for (int i = tid; i < 2*64*32; i += 64) g_flags[i >> 11][i & 2047] = 0;
    }
    int4 c = ((const int4*)conv)[b*T_ + t];
    const float4* T4 = (const float4*)table;
    float4 v = make_float4(0.f,0.f,0.f,0.f);
    int idx[4] = {c.x, c.y, c.z, c.w};
    #pragma unroll
    for (int m = 0; m < 4; ++m) {
        float4 e = T4[(size_t)idx[m]*64 + tid];
        v.x += e.x; v.y += e.y; v.z += e.z; v.w += e.w;
    }
    ((float4*)g_emb)[(size_t)bx*64 + tid] = v;
}

// ---------------- fp32 GEMM: C = A @ W^T + bias ----------------
template<int AT, int GX, int SRC, int DST>
__global__ void __launch_bounds__(256) gemm_kernel(
        const float* __restrict__ W, const float* __restrict__ bias,
        int M, int N, int K) {
    const float* A = (SRC == 0) ? g_emb : g_outsT;
    float* C = (DST == 0) ? g_gx[0] : (DST == 1) ? g_gx[1] : g_rnn;
    __shared__ float As[16][64];
    __shared__ float Bs[16][64];
    int tid = threadIdx.x;
    int n0 = blockIdx.x * 64, m0 = blockIdx.y * 64;
    int ty = tid >> 4, tx = tid & 15;
    float acc[4][4];
    #pragma unroll
    for (int i = 0; i < 4; ++i)
        #pragma unroll
        for (int j = 0; j < 4; ++j) acc[i][j] = 0.f;

    for (int k0 = 0; k0 < K; k0 += 16) {
        if (AT == 0) {
            int m = tid >> 2, kk = (tid & 3) * 4;
            float4 a = *(const float4*)&A[(size_t)(m0+m)*K + k0 + kk];
            As[kk+0][m] = a.x; As[kk+1][m] = a.y; As[kk+2][m] = a.z; As[kk+3][m] = a.w;
        } else {
            int k = tid >> 4, m4 = (tid & 15) * 4;
            float4 a = *(const float4*)&A[(size_t)(k0+k)*M + m0 + m4];
            *(float4*)&As[k][m4] = a;
        }
        {
            int n = tid >> 2, kk = (tid & 3) * 4;
            float4 w = *(const float4*)&W[(size_t)(n0+n)*K + k0 + kk];
            Bs[kk+0][n] = w.x; Bs[kk+1][n] = w.y; Bs[kk+2][n] = w.z; Bs[kk+3][n] = w.w;
        }
        __syncthreads();
        #pragma unroll
        for (int kk = 0; kk < 16; ++kk) {
            float a[4], bb[4];
            #pragma unroll
            for (int j = 0; j < 4; ++j) { a[j] = As[kk][ty*4+j]; bb[j] = Bs[kk][tx*4+j]; }
            #pragma unroll
            for (int i = 0; i < 4; ++i)
                #pragma unroll
                for (int j = 0; j < 4; ++j) acc[i][j] = fmaf(a[i], bb[j], acc[i][j]);
        }
        __syncthreads();
    }
    #pragma unroll
    for (int i = 0; i < 4; ++i) {
        #pragma unroll
        for (int j = 0; j < 4; ++j) {
            int m = m0 + ty*4 + i, n = n0 + tx*4 + j;
            float v = acc[i][j] + bias[n];
            if (GX) C[(size_t)(m >> 5)*((size_t)N*32) + (size_t)n*32 + (m & 31)] = v;
            else    C[(size_t)m*N + n] = v;
        }
    }
}

// ---------------- GRU: 128 blocks (64 d-slices/dir), 256 thr, k-split x2 ----------------
__global__ void __launch_bounds__(256, 1) gru_kernel(
        const float* __restrict__ Whh_f, const float* __restrict__ Whh_b,
        const float* __restrict__ bhh_f, const float* __restrict__ bhh_b) {
    int blk = blockIdx.x;
    int dir = blk >> 6;
    int slice = blk & 63;
    int d0 = slice * 4;
    int tid = threadIdx.x;
    int w  = tid >> 5;        // 0..7
    int di = w & 3;           // d offset (also SMSP id)
    int kh = w >> 2;          // k-half 0/1
    int b  = tid & 31;        // lane == batch
    int d  = d0 + di;

    const float* Whh = dir ? Whh_b : Whh_f;
    const float* bhh = dir ? bhh_b : bhh_f;
    const float* gx  = g_gx[dir];

    __shared__ __align__(16) float w_s[12*256];     // [g*4 + di][k]
    __shared__ __align__(16) float h_s[32*260];     // [b][k], pad 260
    __shared__ float part[3][4][32];                // kh=1 partials [gate][di][b]
    __shared__ float bsh[12];

    for (int i = tid; i < 3072; i += 256) {
        int g = i >> 10; int r = i & 1023; int dd = r >> 8; int k = r & 255;
        w_s[(g*4 + dd)*256 + k] = Whh[(size_t)(g*256 + d0 + dd)*256 + k];
    }
    if (tid < 12) { int g = tid >> 2, dd = tid & 3; bsh[tid] = bhh[g*256 + d0 + dd]; }
    __syncthreads();

    float biasR = bsh[0*4 + di], biasZ = bsh[1*4 + di], biasN = bsh[2*4 + di];
    const ulonglong2* wr2 = (const ulonglong2*)&w_s[(0*4 + di)*256] + kh*32;
    const ulonglong2* wz2 = (const ulonglong2*)&w_s[(1*4 + di)*256] + kh*32;
    const ulonglong2* wn2 = (const ulonglong2*)&w_s[(2*4 + di)*256] + kh*32;
    unsigned* myflag = &g_flags[dir][slice*32];
    const unsigned* pollflag = &g_flags[dir][(tid & 63)*32];

    for (int s = 0; s < T_; ++s) {
        int t = dir ? (T_-1 - s) : s;
        // hoist gx loads (independent of h) above the wait; only kh==0 computes gates
        float xr = 0.f, xz = 0.f, xn = 0.f;
        if (kh == 0) {
            const float* gxt = gx + (size_t)t*768*32;
            xr = gxt[(0*256 + d)*32 + b];
            xz = gxt[(1*256 + d)*32 + b];
            xn = gxt[(2*256 + d)*32 + b];
        }

        float aRf = 0.f, aZf = 0.f, aNf = 0.f, hprev = 0.f;

        if (s > 0) {
            if (tid < 64) {
                unsigned v;
                do {
                    asm volatile("ld.relaxed.gpu.u32 %0, [%1];" : "=r"(v) : "l"(pollflag) : "memory");
                } while (v < (unsigned)s);
                asm volatile("fence.acq_rel.gpu;" ::: "memory");
            }
            __syncthreads();
            // stage h (phase s&1) into smem: coalesced __ldcg + conflict-free STS
            const float4* hx4 = (const float4*)g_hx[dir][s & 1];
            #pragma unroll
            for (int i = 0; i < 8; ++i) {
                int idx = tid + i*256;            // 2048 float4s
                float4 hv = __ldcg(&hx4[idx]);
                int bb = idx >> 6, c = idx & 63;
                *(float4*)&h_s[bb*260 + c*4] = hv;
            }
            __syncthreads();

            const ulonglong2* hp = (const ulonglong2*)&h_s[b*260] + kh*32;
            unsigned long long aR = 0ull, aZ = 0ull, aN = 0ull;
            #pragma unroll 8
            for (int k = 0; k < 32; ++k) {
                ulonglong2 hv = hp[k];
                ulonglong2 r2 = wr2[k], z2 = wz2[k], n2 = wn2[k];
                aR = ffma2(hv.x, r2.x, aR); aR = ffma2(hv.y, r2.y, aR);
                aZ = ffma2(hv.x, z2.x, aZ); aZ = ffma2(hv.y, z2.y, aZ);
                aN = ffma2(hv.x, n2.x, aN); aN = ffma2(hv.y, n2.y, aN);
            }
            aRf = f2sum(aR); aZf = f2sum(aZ); aNf = f2sum(aN);
            if (kh == 1) {
                part[0][di][b] = aRf; part[1][di][b] = aZf; part[2][di][b] = aNf;
            }
            hprev = h_s[b*260 + d];
            __syncthreads();
            if (kh == 0) {
                aRf += part[0][di][b]; aZf += part[1][di][b]; aNf += part[2][di][b];
            }
        }

        if (kh == 0) {
            float r = 1.f / (1.f + __expf(-(xr + aRf + biasR)));
            float z = 1.f / (1.f + __expf(-(xz + aZf + biasZ)));
            float narg = xn + r * (aNf + biasN);
            float e2 = __expf(2.f * narg);
            float n = (e2 - 1.f) / (e2 + 1.f);
            float h2 = (1.f - z) * n + z * hprev;

            g_hx[dir][(s + 1) & 1][b*256 + d] = h2;     // next-phase exchange
            g_outsT[(size_t)(dir*256 + d)*4096 + t*32 + b] = h2;
        }
        __syncthreads();
        if (tid == 0) {
            unsigned nv = (unsigned)(s + 1);
            asm volatile("st.release.gpu.u32 [%0], %1;" :: "l"(myflag), "r"(nv) : "memory");
        }
    }
}

// ---------------- hidden = concat(hT_f, hT_b) @ W_w^T + W_b ; u = hidden ----------------
__global__ void hidden_kernel(const float* __restrict__ W_w, const float* __restrict__ W_b) {
    int b = blockIdx.x;
    int tid = threadIdx.x, wid = tid >> 5, lane = tid & 31;
    __shared__ float a_s[512];
    a_s[tid]       = g_outsT[(size_t)tid*4096 + (T_-1)*32 + b];      // hT_f
    a_s[256 + tid] = g_outsT[(size_t)(256 + tid)*4096 + 0*32 + b];   // hT_b (stored at t=0)
    __syncthreads();
    for (int dd = wid; dd < 256; dd += 8) {
        const float4* wrow = (const float4*)&W_w[(size_t)dd*512];
        float acc = 0.f;
        #pragma unroll
        for (int i = 0; i < 4; ++i) {
            float4 wv = wrow[lane + i*32];
            float4 av = *(const float4*)&a_s[(lane + i*32)*4];
            acc = fmaf(wv.x, av.x, acc); acc = fmaf(wv.y, av.y, acc);
            acc = fmaf(wv.z, av.z, acc); acc = fmaf(wv.w, av.w, acc);
        }
        #pragma unroll
        for (int o = 16; o > 0; o >>= 1) acc += __shfl_xor_sync(0xffffffffu, acc, o);
        if (lane == 0) {
            float v = acc + W_b[dd];
            g_hidden[b*256 + dd] = v;
            g_u[b*256 + dd] = v;
        }
    }
}

// ---------------- E[h][b][l][:] = embed_bag(C_tables[h]) + add_lm(rnn_out) ----------------
__global__ void ebuild_kernel(const int* __restrict__ src, const float* __restrict__ C,
                              const int* __restrict__ kb, const int* __restrict__ cl) {
    int bl = blockIdx.x;               // b*512 + l
    int b = bl >> 9, l = bl & 511;
    int tid = threadIdx.x;             // 64 threads, float4 each
    int4 s = ((const int4*)src)[bl];
    int rel = l - kb[b];
    bool valid = (rel >= 0) && (rel < cl[b]);
    int rc = min(max(rel, 0), T_ - 1);
    float4 base = make_float4(0.f,0.f,0.f,0.f);
    if (valid) base = ((const float4*)g_rnn)[(size_t)(rc*32 + b)*64 + tid];
    const float4* C4 = (const float4*)C;
    int idx[4] = {s.x, s.y, s.z, s.w};
    #pragma unroll
    for (int h = 0; h < 4; ++h) {
        float4 v = base;
        #pragma unroll
        for (int m = 0; m < 4; ++m) {
            float4 e = C4[((size_t)h*V_ + idx[m])*64 + tid];
            v.x += e.x; v.y += e.y; v.z += e.z; v.w += e.w;
        }
        ((float4*)g_E)[(((size_t)h*B_ + b)*L_ + l)*64 + tid] = v;
    }
}

// ---------------- hop: logits + softmax (+ sigmoid to d_out on last hop) ----------------
__global__ void hop_logit_kernel(int hop, float* __restrict__ out) {
    int b = blockIdx.x;
    int tid = threadIdx.x, wid = tid >> 5, lane = tid & 31;
    __shared__ float u_s[256];
    __shared__ float logit_s[512];
    __shared__ float red_s[8];
    u_s[tid] = g_u[b*256 + tid];
    __syncthreads();
    const float4* u4 = (const float4*)u_s;
    for (int l = wid; l < 512; l += 8) {
        const float4* row = (const float4*)&g_E[(((size_t)hop*B_ + b)*L_ + l)*D_];
        float acc = 0.f;
        #pragma unroll
        for (int i = 0; i < 2; ++i) {
            float4 e = row[lane + i*32];
            float4 uu = u4[lane + i*32];
            acc = fmaf(e.x, uu.x, acc); acc = fmaf(e.y, uu.y, acc);
            acc = fmaf(e.z, uu.z, acc); acc = fmaf(e.w, uu.w, acc);
        }
        #pragma unroll
        for (int o = 16; o > 0; o >>= 1) acc += __shfl_xor_sync(0xffffffffu, acc, o);
        if (lane == 0) logit_s[l] = acc;
    }
    __syncthreads();
    float l0 = logit_s[tid], l1 = logit_s[tid + 256];
    float m = fmaxf(l0, l1);
    #pragma unroll
    for (int o = 16; o > 0; o >>= 1) m = fmaxf(m, __shfl_xor_sync(0xffffffffu, m, o));
    if (lane == 0) red_s[wid] = m;
    __syncthreads();
    float M = red_s[0];
    #pragma unroll
    for (int i = 1; i < 8; ++i) M = fmaxf(M, red_s[i]);
    __syncthreads();
    float e0 = expf(l0 - M), e1 = expf(l1 - M);
    float ssum = e0 + e1;
    #pragma unroll
    for (int o = 16; o > 0; o >>= 1) ssum += __shfl_xor_sync(0xffffffffu, ssum, o);
    if (lane == 0) red_s[wid] = ssum;
    __syncthreads();
    float S = 0.f;
    #pragma unroll
    for (int i = 0; i < 8; ++i) S += red_s[i];
    float inv = 1.f / S;
    g_prob[b*512 + tid]       = e0 * inv;
    g_prob[b*512 + tid + 256] = e1 * inv;
    if (hop == 2) {
        out[b*512 + tid]       = 1.f / (1.f + expf(-l0));
        out[b*512 + tid + 256] = 1.f / (1.f + expf(-l1));
    }
}

// ---------------- hop: u += E[hop+1]^T @ prob ----------------
__global__ void hop_agg_kernel(int hop) {
    int b = blockIdx.x, d = threadIdx.x;   // 256 threads
    __shared__ float p_s[512];
    p_s[d]       = g_prob[b*512 + d];
    p_s[d + 256] = g_prob[b*512 + d + 256];
    __syncthreads();
    const float* E = &g_E[(((size_t)(hop+1)*B_ + b)*L_)*D_];
    float acc = 0.f;
    #pragma unroll 8
    for (int l = 0; l < 512; ++l) acc = fmaf(p_s[l], E[(size_t)l*256 + d], acc);
    g_u[b*256 + d] += acc;
}

// ---------------- encoded = relu(concat(hidden, u) @ proj^T + pb) ----------------
__global__ void encoded_kernel(const float* __restrict__ pw, const float* __restrict__ pb,
                               float* __restrict__ out) {
    int b = blockIdx.x;
    int tid = threadIdx.x, wid = tid >> 5, lane = tid & 31;
    __shared__ float a_s[512];
    a_s[tid]       = g_hidden[b*256 + tid];
    a_s[256 + tid] = g_u[b*256 + tid];
    __syncthreads();
    for (int dd = wid; dd < 256; dd += 8) {
        const float4* wrow = (const float4*)&pw[(size_t)dd*512];
        float acc = 0.f;
        #pragma unroll
        for (int i = 0; i < 4; ++i) {
            float4 wv = wrow[lane + i*32];
            float4 av = *(const float4*)&a_s[(lane + i*32)*4];
            acc = fmaf(wv.x, av.x, acc); acc = fmaf(wv.y, av.y, acc);
            acc = fmaf(wv.z, av.z, acc); acc = fmaf(wv.w, av.w, acc);
        }
        #pragma unroll
        for (int o = 16; o > 0; o >>= 1) acc += __shfl_xor_sync(0xffffffffu, acc, o);
        if (lane == 0) out[16384 + b*256 + dd] = fmaxf(acc + pb[dd], 0.f);
    }
}

// ---------------- launch ----------------
extern "C" void kernel_launch(void* const* d_in, const int* in_sizes, int n_in,
                              void* d_out, int out_size) {
    const int*   conv_seqs = (const int*)  d_in[0];
    const int*   src_seqs  = (const int*)  d_in[1];
    const int*   kb_len    = (const int*)  d_in[2];
    const int*   conv_len  = (const int*)  d_in[3];
    const float* emb_ctx   = (const float*)d_in[4];
    const float* C_tables  = (const float*)d_in[5];
    const float* Wih_f     = (const float*)d_in[6];
    const float* Whh_f     = (const float*)d_in[7];
    const float* bih_f     = (const float*)d_in[8];
    const float* bhh_f     = (const float*)d_in[9];
    const float* Wih_b     = (const float*)d_in[10];
    const float* Whh_b     = (const float*)d_in[11];
    const float* bih_b     = (const float*)d_in[12];
    const float* bhh_b     = (const float*)d_in[13];
    const float* W_w       = (const float*)d_in[14];
    const float* W_b       = (const float*)d_in[15];
    const float* proj_w    = (const float*)d_in[16];
    const float* proj_b    = (const float*)d_in[17];
    float* out = (float*)d_out;

    embed_conv_kernel<<<T_*B_, 64>>>(conv_seqs, emb_ctx);
    gemm_kernel<0,1,0,0><<<dim3(12, 64), 256>>>(Wih_f, bih_f, 4096, 768, 256);
    gemm_kernel<0,1,0,1><<<dim3(12, 64), 256>>>(Wih_b, bih_b, 4096, 768, 256);
    gru_kernel<<<128, 256>>>(Whh_f, Whh_b, bhh_f, bhh_b);
    hidden_kernel<<<32, 256>>>(W_w, W_b);
    gemm_kernel<1,0,1,2><<<dim3(4, 64), 256>>>(W_w, W_b, 4096, 256, 512);
    ebuild_kernel<<<B_*L_, 64>>>(src_seqs, C_tables, kb_len, conv_len);
    for (int hop = 0; hop < 3; ++hop) {
        hop_logit_kernel<<<32, 256>>>(hop, out);
        hop_agg_kernel<<<32, 256>>>(hop);
    }
    encoded_kernel<<<32, 256>>>(proj_w, proj_b, out);
}